// round 14
// baseline (speedup 1.0000x reference)
#include <cuda_runtime.h>
#include <cstdint>

// Problem constants (BATCH=4, SEQ=4096, DIM=1024)
#define B 4
#define L 4096
#define D 1024
#define C  64                 // chunk length
#define NC 64                 // chunks along L (NC*C == L)
#define TPB 256               // threads per block, 2 dims each
#define DBLK 2                // dim blocks (DBLK*TPB*2 == D)
#define G 4                   // load-group size
#define BLKS_PER_B (DBLK * NC)   // 128 K1 blocks per batch

// Scratch (__device__ globals: allocation-free rule)
__device__ float2 g_totals[B * NC * D];
__device__ float2 g_carry [B * NC * D];
__device__ unsigned g_ctr[B];          // zero-init at load; self-resetting

__device__ __forceinline__ float2 cmul(float2 u, float2 v) {
    return make_float2(fmaf(u.x, v.x, -u.y * v.y), fmaf(u.x, v.y, u.y * v.x));
}

__device__ __forceinline__ float2 decay(float r, float im) {
    float mag = sqrtf(fmaf(r, r, im * im));
    float s = __expf(-mag) / mag;
    return make_float2(r * s, im * s);
}

// ---- K1: zero-init local chunk scans -> totals; last block per batch
//      runs that batch's carry chains (fused K2). ----
__global__ void __launch_bounds__(TPB, 4)
k1_totals_tail(const float* __restrict__ x,
               const float* __restrict__ pr, const float* __restrict__ pi,
               const float* __restrict__ ir, const float* __restrict__ ii,
               const float* __restrict__ lr, const float* __restrict__ li)
{
    const int d0    = (blockIdx.x * TPB + threadIdx.x) * 2;
    const int chunk = blockIdx.y;
    const int b     = blockIdx.z;

    {
        const float* xp = x + ((size_t)(b * L + chunk * C)) * D + d0;

        const float2 a0 = decay(pr[d0],     pi[d0]);
        const float2 a1 = decay(pr[d0 + 1], pi[d0 + 1]);
        const float2 cre = *(const float2*)(ir + d0);
        const float2 cim = *(const float2*)(ii + d0);

        float h0r = 0.f, h0i = 0.f, h1r = 0.f, h1i = 0.f;
#pragma unroll
        for (int g = 0; g < C / G; g++) {
            float2 xv[G];
#pragma unroll
            for (int k = 0; k < G; k++)
                xv[k] = *(const float2*)(xp + (size_t)(g * G + k) * D);
#pragma unroll
            for (int k = 0; k < G; k++) {
                float n0r = fmaf(a0.x, h0r, fmaf(-a0.y, h0i, cre.x * xv[k].x));
                float n0i = fmaf(a0.x, h0i, fmaf( a0.y, h0r, cim.x * xv[k].x));
                float n1r = fmaf(a1.x, h1r, fmaf(-a1.y, h1i, cre.y * xv[k].y));
                float n1i = fmaf(a1.x, h1i, fmaf( a1.y, h1r, cim.y * xv[k].y));
                h0r = n0r; h0i = n0i; h1r = n1r; h1i = n1i;
            }
        }
        *(float4*)&g_totals[((size_t)b * NC + chunk) * D + d0] =
            make_float4(h0r, h0i, h1r, h1i);
    }

    // ---- Completion counting (threadFenceReduction pattern) ----
    __shared__ bool s_last;
    __threadfence();
    __syncthreads();
    if (threadIdx.x == 0)
        s_last = (atomicAdd(&g_ctr[b], 1u) == BLKS_PER_B - 1);
    __syncthreads();
    if (!s_last) return;

    if (threadIdx.x == 0) g_ctr[b] = 0;    // reset for next graph replay
    __threadfence();                        // acquire: totals now visible

    // ---- Fused K2: carry chains for batch b. 256 threads x 2 pairs each. ----
    const int pA = threadIdx.x;            // pair 0..255 -> dims 2pA, 2pA+1
    const int pB = threadIdx.x + TPB;      // pair 256..511
    const int dA = pA * 2, dB = pB * 2;

    float2 aA0 = decay(pr[dA], pi[dA]),     aA1 = decay(pr[dA + 1], pi[dA + 1]);
    float2 aB0 = decay(pr[dB], pi[dB]),     aB1 = decay(pr[dB + 1], pi[dB + 1]);
#pragma unroll
    for (int k = 0; k < 6; k++) {          // a^64
        aA0 = cmul(aA0, aA0); aA1 = cmul(aA1, aA1);
        aB0 = cmul(aB0, aB0); aB1 = cmul(aB1, aB1);
    }

    float A0r = lr[b * D + dA],     A0i = li[b * D + dA];
    float A1r = lr[b * D + dA + 1], A1i = li[b * D + dA + 1];
    float B0r = lr[b * D + dB],     B0i = li[b * D + dB];
    float B1r = lr[b * D + dB + 1], B1i = li[b * D + dB + 1];

#pragma unroll 1
    for (int base = 0; base < NC; base += 4) {
        float4 TA[4], TB[4];
#pragma unroll
        for (int k = 0; k < 4; k++) {
            TA[k] = *(const float4*)&g_totals[((size_t)b * NC + base + k) * D + dA];
            TB[k] = *(const float4*)&g_totals[((size_t)b * NC + base + k) * D + dB];
        }
#pragma unroll
        for (int k = 0; k < 4; k++) {
            const size_t row = ((size_t)b * NC + base + k) * D;
            *(float4*)&g_carry[row + dA] = make_float4(A0r, A0i, A1r, A1i);
            *(float4*)&g_carry[row + dB] = make_float4(B0r, B0i, B1r, B1i);
            float n;
            n   = fmaf(aA0.x, A0r, fmaf(-aA0.y, A0i, TA[k].x));
            A0i = fmaf(aA0.x, A0i, fmaf( aA0.y, A0r, TA[k].y)); A0r = n;
            n   = fmaf(aA1.x, A1r, fmaf(-aA1.y, A1i, TA[k].z));
            A1i = fmaf(aA1.x, A1i, fmaf( aA1.y, A1r, TA[k].w)); A1r = n;
            n   = fmaf(aB0.x, B0r, fmaf(-aB0.y, B0i, TB[k].x));
            B0i = fmaf(aB0.x, B0i, fmaf( aB0.y, B0r, TB[k].y)); B0r = n;
            n   = fmaf(aB1.x, B1r, fmaf(-aB1.y, B1i, TB[k].z));
            B1i = fmaf(aB1.x, B1i, fmaf( aB1.y, B1r, TB[k].w)); B1r = n;
        }
    }
}

// ---- K3: exact scan seeded with carry; streaming stores. (R9 shape) ----
__global__ void __launch_bounds__(TPB, 4)
k3_scan(const float* __restrict__ x,
        const float* __restrict__ pr, const float* __restrict__ pi,
        const float* __restrict__ ir, const float* __restrict__ ii,
        float* __restrict__ out)
{
    const int d0    = (blockIdx.x * TPB + threadIdx.x) * 2;
    const int chunk = blockIdx.y;
    const int b     = blockIdx.z;

    const size_t base = ((size_t)(b * L + chunk * C)) * D + d0;
    const float* xp = x + base;
    float* op = out + base;

    const float2 a0 = decay(pr[d0],     pi[d0]);
    const float2 a1 = decay(pr[d0 + 1], pi[d0 + 1]);
    const float2 cre = *(const float2*)(ir + d0);
    const float2 cim = *(const float2*)(ii + d0);

    float4 h0 = *(const float4*)&g_carry[((size_t)b * NC + chunk) * D + d0];
    float h0r = h0.x, h0i = h0.y, h1r = h0.z, h1i = h0.w;

#pragma unroll
    for (int g = 0; g < C / G; g++) {
        float2 xv[G];
#pragma unroll
        for (int k = 0; k < G; k++)
            xv[k] = *(const float2*)(xp + (size_t)(g * G + k) * D);
#pragma unroll
        for (int k = 0; k < G; k++) {
            float n0r = fmaf(a0.x, h0r, fmaf(-a0.y, h0i, cre.x * xv[k].x));
            float n0i = fmaf(a0.x, h0i, fmaf( a0.y, h0r, cim.x * xv[k].x));
            float n1r = fmaf(a1.x, h1r, fmaf(-a1.y, h1i, cre.y * xv[k].y));
            float n1i = fmaf(a1.x, h1i, fmaf( a1.y, h1r, cim.y * xv[k].y));
            h0r = n0r; h0i = n0i; h1r = n1r; h1i = n1i;
            __stcs((float2*)(op + (size_t)(g * G + k) * D), make_float2(h0r, h1r));
        }
    }
}

extern "C" void kernel_launch(void* const* d_in, const int* in_sizes, int n_in,
                              void* d_out, int out_size) {
    const float* x    = (const float*)d_in[0];
    const float* p_re = (const float*)d_in[1];
    const float* p_im = (const float*)d_in[2];
    const float* i_re = (const float*)d_in[3];
    const float* i_im = (const float*)d_in[4];
    const float* lc_r = (const float*)d_in[5];
    const float* lc_i = (const float*)d_in[6];
    float* out = (float*)d_out;

    dim3 grid(DBLK, NC, B);   // (2, 64, 4) = 512 blocks x 256 threads
    k1_totals_tail<<<grid, TPB>>>(x, p_re, p_im, i_re, i_im, lc_r, lc_i);
    k3_scan<<<grid, TPB>>>(x, p_re, p_im, i_re, i_im, out);
}

// round 15
// speedup vs baseline: 1.2577x; 1.2577x over previous
#include <cuda_runtime.h>
#include <cstdint>

// Problem constants (BATCH=4, SEQ=4096, DIM=1024)
#define B 4
#define L 4096
#define D 1024
#define C  64                 // chunk length
#define NC 64                 // chunks along L (NC*C == L)
#define TPB 256               // threads per block, 2 dims each
#define DBLK 2                // dim blocks (DBLK*TPB*2 == D)
#define G 4                   // load-group size

// Scratch (__device__ globals: allocation-free rule). 2 MB each.
__device__ float2 g_totals[B * NC * D];
__device__ float2 g_carry [B * NC * D];

__device__ __forceinline__ float2 cmul(float2 u, float2 v) {
    return make_float2(fmaf(u.x, v.x, -u.y * v.y), fmaf(u.x, v.y, u.y * v.x));
}

__device__ __forceinline__ float2 decay(float r, float im) {
    float mag = sqrtf(fmaf(r, r, im * im));
    float s = __expf(-mag) / mag;
    return make_float2(r * s, im * s);
}

// ---- K1: zero-init local chunk scans -> totals. 2 dims/thread, group-4 MLP. ----
__global__ void __launch_bounds__(TPB, 4)
k1_totals(const float* __restrict__ x,
          const float* __restrict__ pr, const float* __restrict__ pi,
          const float* __restrict__ ir, const float* __restrict__ ii)
{
    const int d0    = (blockIdx.x * TPB + threadIdx.x) * 2;
    const int chunk = blockIdx.y;
    const int b     = blockIdx.z;

    const float* xp = x + ((size_t)(b * L + chunk * C)) * D + d0;

    const float2 a0 = decay(pr[d0],     pi[d0]);
    const float2 a1 = decay(pr[d0 + 1], pi[d0 + 1]);
    const float2 cre = *(const float2*)(ir + d0);
    const float2 cim = *(const float2*)(ii + d0);

    float h0r = 0.f, h0i = 0.f, h1r = 0.f, h1i = 0.f;

#pragma unroll
    for (int g = 0; g < C / G; g++) {
        float2 xv[G];
#pragma unroll
        for (int k = 0; k < G; k++)
            xv[k] = *(const float2*)(xp + (size_t)(g * G + k) * D);
#pragma unroll
        for (int k = 0; k < G; k++) {
            float n0r = fmaf(a0.x, h0r, fmaf(-a0.y, h0i, cre.x * xv[k].x));
            float n0i = fmaf(a0.x, h0i, fmaf( a0.y, h0r, cim.x * xv[k].x));
            float n1r = fmaf(a1.x, h1r, fmaf(-a1.y, h1i, cre.y * xv[k].y));
            float n1i = fmaf(a1.x, h1i, fmaf( a1.y, h1r, cim.y * xv[k].y));
            h0r = n0r; h0i = n0i; h1r = n1r; h1i = n1i;
        }
    }
    *(float4*)&g_totals[((size_t)b * NC + chunk) * D + d0] =
        make_float4(h0r, h0i, h1r, h1i);
}

// ---- K2: serial carry propagation per (b,2-dims), float4 totals, batched. ----
__global__ void __launch_bounds__(512)
k2_carries(const float* __restrict__ pr, const float* __restrict__ pi,
           const float* __restrict__ lr, const float* __restrict__ li)
{
    const int gid = blockIdx.x * blockDim.x + threadIdx.x;   // 0..2047
    if (gid >= B * D / 2) return;
    const int b  = gid / (D / 2);
    const int d0 = (gid % (D / 2)) * 2;

    float2 aA = decay(pr[d0],     pi[d0]);
    float2 aB = decay(pr[d0 + 1], pi[d0 + 1]);
#pragma unroll
    for (int k = 0; k < 6; k++) { aA = cmul(aA, aA); aB = cmul(aB, aB); }  // a^64

    float H0r = lr[b * D + d0],     H0i = li[b * D + d0];
    float H1r = lr[b * D + d0 + 1], H1i = li[b * D + d0 + 1];

#pragma unroll
    for (int base = 0; base < NC; base += 16) {
        float4 Tb[16];
#pragma unroll
        for (int k = 0; k < 16; k++)
            Tb[k] = __ldg((const float4*)&g_totals[((size_t)b * NC + base + k) * D + d0]);
#pragma unroll
        for (int k = 0; k < 16; k++) {
            __stcs((float4*)&g_carry[((size_t)b * NC + base + k) * D + d0],
                   make_float4(H0r, H0i, H1r, H1i));
            float n0r = fmaf(aA.x, H0r, fmaf(-aA.y, H0i, Tb[k].x));
            float n0i = fmaf(aA.x, H0i, fmaf( aA.y, H0r, Tb[k].y));
            float n1r = fmaf(aB.x, H1r, fmaf(-aB.y, H1i, Tb[k].z));
            float n1i = fmaf(aB.x, H1i, fmaf( aB.y, H1r, Tb[k].w));
            H0r = n0r; H0i = n0i; H1r = n1r; H1i = n1i;
        }
    }
}

// ---- K3: exact scan seeded with carry; group-4 loads + streaming stores. ----
__global__ void __launch_bounds__(TPB, 4)
k3_scan(const float* __restrict__ x,
        const float* __restrict__ pr, const float* __restrict__ pi,
        const float* __restrict__ ir, const float* __restrict__ ii,
        float* __restrict__ out)
{
    const int d0    = (blockIdx.x * TPB + threadIdx.x) * 2;
    const int chunk = blockIdx.y;
    const int b     = blockIdx.z;

    const size_t base = ((size_t)(b * L + chunk * C)) * D + d0;
    const float* xp = x + base;
    float* op = out + base;

    const float2 a0 = decay(pr[d0],     pi[d0]);
    const float2 a1 = decay(pr[d0 + 1], pi[d0 + 1]);
    const float2 cre = *(const float2*)(ir + d0);
    const float2 cim = *(const float2*)(ii + d0);

    float4 h0 = *(const float4*)&g_carry[((size_t)b * NC + chunk) * D + d0];
    float h0r = h0.x, h0i = h0.y, h1r = h0.z, h1i = h0.w;

#pragma unroll
    for (int g = 0; g < C / G; g++) {
        float2 xv[G];
#pragma unroll
        for (int k = 0; k < G; k++)
            xv[k] = *(const float2*)(xp + (size_t)(g * G + k) * D);
#pragma unroll
        for (int k = 0; k < G; k++) {
            float n0r = fmaf(a0.x, h0r, fmaf(-a0.y, h0i, cre.x * xv[k].x));
            float n0i = fmaf(a0.x, h0i, fmaf( a0.y, h0r, cim.x * xv[k].x));
            float n1r = fmaf(a1.x, h1r, fmaf(-a1.y, h1i, cre.y * xv[k].y));
            float n1i = fmaf(a1.x, h1i, fmaf( a1.y, h1r, cim.y * xv[k].y));
            h0r = n0r; h0i = n0i; h1r = n1r; h1i = n1i;
            __stcs((float2*)(op + (size_t)(g * G + k) * D), make_float2(h0r, h1r));
        }
    }
}

extern "C" void kernel_launch(void* const* d_in, const int* in_sizes, int n_in,
                              void* d_out, int out_size) {
    const float* x    = (const float*)d_in[0];
    const float* p_re = (const float*)d_in[1];
    const float* p_im = (const float*)d_in[2];
    const float* i_re = (const float*)d_in[3];
    const float* i_im = (const float*)d_in[4];
    const float* lc_r = (const float*)d_in[5];
    const float* lc_i = (const float*)d_in[6];
    float* out = (float*)d_out;

    dim3 grid(DBLK, NC, B);   // (2, 64, 4) = 512 blocks x 256 threads
    k1_totals<<<grid, TPB>>>(x, p_re, p_im, i_re, i_im);
    k2_carries<<<(B * D / 2 + 511) / 512, 512>>>(p_re, p_im, lc_r, lc_i);
    k3_scan<<<grid, TPB>>>(x, p_re, p_im, i_re, i_im, out);
}